// round 1
// baseline (speedup 1.0000x reference)
#include <cuda_runtime.h>

// B=256 batches, N=128 neurons, E=4N=512 state dims.
// Output layout: [ydot (B*512 floats)] [J (B*512*512 floats)]
#define NN 128
#define BB 256
#define EE 512

// -------- scratch (__device__ globals; no allocations allowed) --------
__device__ float  g_negGCC  [NN * NN];   // -g_C[i][j] / C[j], row-major (i major)
__device__ float  g_negGCC_T[NN * NN];   // transpose: [j][i]
__device__ float  g_sumGC;               // sum over all i,j of g_C[i][j]/C[j]
__device__ float4 g_diag4   [NN];        // {0, -1/tau_m, -1/tau_h, -1/tau_n}
__device__ float4 g_state   [BB * NN];   // {dvv, jm, jh, jn} per (b,i)

// ---------------------------------------------------------------------
// Kernel 0: static precompute (batch-independent). 1 block, 256 threads.
// Deterministic reduction (fixed strided accumulation + fixed tree order).
// ---------------------------------------------------------------------
__global__ void prep_kernel(const float* __restrict__ gC,
                            const float* __restrict__ C,
                            const float* __restrict__ tau_m,
                            const float* __restrict__ tau_h,
                            const float* __restrict__ tau_n) {
    __shared__ float red[256];
    int t = threadIdx.x;
    float acc = 0.f;
    for (int k = t; k < NN * NN; k += 256) {
        int j = k & (NN - 1);
        int i = k >> 7;
        float v = gC[k] / C[j];          // gC_over_C[i][j]
        g_negGCC[k]          = -v;
        g_negGCC_T[j * NN + i] = -v;
        acc += v;
    }
    red[t] = acc;
    __syncthreads();
    for (int s = 128; s > 0; s >>= 1) {
        if (t < s) red[t] += red[t + s];
        __syncthreads();
    }
    if (t == 0) g_sumGC = red[0];
    if (t < NN)
        g_diag4[t] = make_float4(0.f, -1.f / tau_m[t], -1.f / tau_h[t], -1.f / tau_n[t]);
}

// ---------------------------------------------------------------------
// Kernel 1: pointwise HH dynamics + coupling matvec.
// Grid: (BB) blocks x NN threads. Thread i of block b handles neuron i.
// Writes ydot and the per-(b,i) Jacobian diagonal coefficients.
// ---------------------------------------------------------------------
__global__ void __launch_bounds__(NN)
point_kernel(const float* __restrict__ y,     const float* __restrict__ Ic,
             const float* __restrict__ C,
             const float* __restrict__ g_Na,  const float* __restrict__ E_Na,
             const float* __restrict__ g_K,   const float* __restrict__ E_K,
             const float* __restrict__ g_L,   const float* __restrict__ E_L,
             const float* __restrict__ m_inf, const float* __restrict__ tau_m,
             const float* __restrict__ h_inf, const float* __restrict__ tau_h,
             const float* __restrict__ n_inf, const float* __restrict__ tau_n,
             float* __restrict__ ydot) {
    const int b = blockIdx.x;
    const int i = threadIdx.x;

    __shared__ float Vs[NN];

    // y[b, 4i .. 4i+3] = {V, m, h, n} : one coalesced float4
    float4 yv = reinterpret_cast<const float4*>(y)[b * NN + i];
    float V = yv.x, m = yv.y, h = yv.z, n = yv.w;
    Vs[i] = V;
    __syncthreads();

    float invC = 1.f / C[i];
    float gna = g_Na[i], gk = g_K[i], gl = g_L[i];
    float m2 = m * m, m3 = m2 * m;
    float n2 = n * n, n3 = n2 * n, n4 = n3 * n;
    float dVNa = V - E_Na[i];
    float dVK  = V - E_K[i];

    // coupling: sum_j g_C[i][j]*invC[j]*(V_i - V_j) = sum_j negGCC[i][j]*(V_j - V_i)
    // read the TRANSPOSE so warps are coalesced (consecutive i at fixed j).
    float acc = 0.f;
    const float* __restrict__ colT = g_negGCC_T;
    #pragma unroll 16
    for (int j = 0; j < NN; j++)
        acc = fmaf(colT[j * NN + i], Vs[j] - V, acc);

    float Vdot = invC * (-gna * m3 * h * dVNa - gk * n4 * dVK - gl * (V - E_L[i]) + Ic[b]) + acc;
    float mdot = (m_inf[i] - m) / tau_m[i];
    float hdot = (h_inf[i] - h) / tau_h[i];
    float ndot = (n_inf[i] - n) / tau_n[i];

    reinterpret_cast<float4*>(ydot)[b * NN + i] = make_float4(Vdot, mdot, hdot, ndot);

    // Jacobian diagonal coefficients for this (b, i)
    float dvv = invC * (-gl - gna * h * m3 - gk * n4);
    float jm  = -invC * 3.f * gna * h * m2 * dVNa;
    float jh  = -invC * gna * m3 * dVNa;
    float jn  = -invC * 4.f * gk * n3 * dVK;
    g_state[b * NN + i] = make_float4(dvv, jm, jh, jn);
}

// ---------------------------------------------------------------------
// Kernel 2: stream-fill the full Jacobian (268 MB of STG.128).
// One thread = one float4 = J[b, r, 4j .. 4j+3].
//   tid = b*512*128 + r*128 + j ; warp-uniform (b, r) -> no divergence on row type.
// Row r = 4i + comp:
//   comp==0 (V row): col group j -> {JVV[b,i,j], d_ij*jm, d_ij*jh, d_ij*jn}
//                    JVV = -gC_over_C[i][j] + d_ij*(sumGC + dvv[b,i])
//   comp in {1,2,3}: all zero except j==i -> component comp = -1/tau_x[i]
// ---------------------------------------------------------------------
__global__ void __launch_bounds__(256)
fill_kernel(float* __restrict__ J) {
    unsigned tid = blockIdx.x * 256u + threadIdx.x;   // < 16,777,216
    int j    = tid & 127;
    int r    = (tid >> 7) & 511;
    int b    = tid >> 16;
    int comp = r & 3;
    int i    = r >> 2;

    float4 out = make_float4(0.f, 0.f, 0.f, 0.f);
    if (comp == 0) {
        float v = g_negGCC[i * NN + j];     // coalesced across the warp (consecutive j)
        if (j == i) {
            float4 st = g_state[b * NN + i];
            v += g_sumGC + st.x;
            out.y = st.y; out.z = st.z; out.w = st.w;
        }
        out.x = v;
    } else if (j == i) {
        float4 d = g_diag4[i];
        float val = (comp == 1) ? d.y : (comp == 2) ? d.z : d.w;
        reinterpret_cast<float*>(&out)[comp] = val;
    }
    reinterpret_cast<float4*>(J)[tid] = out;
}

// ---------------------------------------------------------------------
extern "C" void kernel_launch(void* const* d_in, const int* in_sizes, int n_in,
                              void* d_out, int out_size) {
    const float* y     = (const float*)d_in[0];
    const float* Ic    = (const float*)d_in[1];
    const float* C     = (const float*)d_in[2];
    const float* g_Na  = (const float*)d_in[3];
    const float* E_Na  = (const float*)d_in[4];
    const float* g_K   = (const float*)d_in[5];
    const float* E_K   = (const float*)d_in[6];
    const float* g_L   = (const float*)d_in[7];
    const float* E_L   = (const float*)d_in[8];
    const float* m_inf = (const float*)d_in[9];
    const float* tau_m = (const float*)d_in[10];
    const float* h_inf = (const float*)d_in[11];
    const float* tau_h = (const float*)d_in[12];
    const float* n_inf = (const float*)d_in[13];
    const float* tau_n = (const float*)d_in[14];
    const float* g_C   = (const float*)d_in[15];

    float* out  = (float*)d_out;
    float* ydot = out;                       // B*512 floats
    float* J    = out + (size_t)BB * EE;     // B*512*512 floats

    prep_kernel<<<1, 256>>>(g_C, C, tau_m, tau_h, tau_n);
    point_kernel<<<BB, NN>>>(y, Ic, C, g_Na, E_Na, g_K, E_K, g_L, E_L,
                             m_inf, tau_m, h_inf, tau_h, n_inf, tau_n, ydot);
    // B*512*128 float4s = 16,777,216 threads
    fill_kernel<<<(BB * EE * NN) / 256, 256>>>(J);
}

// round 2
// speedup vs baseline: 1.5072x; 1.5072x over previous
#include <cuda_runtime.h>

// B=256 batches, N=128 neurons, E=4N=512 state dims.
// Output layout: [ydot (B*512 floats)] [J (B*512*512 floats)]
#define NN 128
#define BB 256
#define EE 512

// -------- scratch (__device__ globals; no allocations allowed) --------
__device__ float  g_negGCC  [NN * NN];   // -g_C[i][j] / C[j], row-major (i major)
__device__ float  g_negGCC_T[NN * NN];   // transpose: [j][i]
__device__ float  g_partial [NN];        // per-row partial sums of gC_over_C
__device__ float  g_sumGC;               // sum over all i,j of g_C[i][j]/C[j]
__device__ float4 g_diag4   [NN];        // {0, -1/tau_m, -1/tau_h, -1/tau_n}
__device__ float4 g_state   [BB * NN];   // {dvv, jm, jh, jn} per (b,i)

// ---------------------------------------------------------------------
// Kernel 0a: wide static precompute. 128 blocks x 128 threads,
// block i / thread j handles gC[i][j]. One load+div per thread -> fully
// latency-overlapped. Per-block deterministic shared-tree partial sum.
// ---------------------------------------------------------------------
__global__ void __launch_bounds__(NN)
prep_wide_kernel(const float* __restrict__ gC, const float* __restrict__ C) {
    __shared__ float red[NN];
    const int i = blockIdx.x;
    const int j = threadIdx.x;
    const int k = i * NN + j;

    float v = gC[k] / C[j];          // gC_over_C[i][j]
    g_negGCC[k]            = -v;
    g_negGCC_T[j * NN + i] = -v;

    red[j] = v;
    __syncthreads();
    #pragma unroll
    for (int s = 64; s > 0; s >>= 1) {
        if (j < s) red[j] += red[j + s];
        __syncthreads();
    }
    if (j == 0) g_partial[i] = red[0];
}

// ---------------------------------------------------------------------
// Kernel 0b: deterministic final reduce of 128 partials + diag table.
// 1 block x 128 threads (tiny; all inputs L2-hot by now).
// ---------------------------------------------------------------------
__global__ void __launch_bounds__(NN)
prep_reduce_kernel(const float* __restrict__ tau_m,
                   const float* __restrict__ tau_h,
                   const float* __restrict__ tau_n) {
    __shared__ float red[NN];
    const int t = threadIdx.x;
    red[t] = g_partial[t];
    __syncthreads();
    #pragma unroll
    for (int s = 64; s > 0; s >>= 1) {
        if (t < s) red[t] += red[t + s];
        __syncthreads();
    }
    if (t == 0) g_sumGC = red[0];
    g_diag4[t] = make_float4(0.f, -1.f / tau_m[t], -1.f / tau_h[t], -1.f / tau_n[t]);
}

// ---------------------------------------------------------------------
// Kernel 1: pointwise HH dynamics + coupling matvec.
// Grid: (BB) blocks x NN threads. Thread i of block b handles neuron i.
// ---------------------------------------------------------------------
__global__ void __launch_bounds__(NN)
point_kernel(const float* __restrict__ y,     const float* __restrict__ Ic,
             const float* __restrict__ C,
             const float* __restrict__ g_Na,  const float* __restrict__ E_Na,
             const float* __restrict__ g_K,   const float* __restrict__ E_K,
             const float* __restrict__ g_L,   const float* __restrict__ E_L,
             const float* __restrict__ m_inf, const float* __restrict__ tau_m,
             const float* __restrict__ h_inf, const float* __restrict__ tau_h,
             const float* __restrict__ n_inf, const float* __restrict__ tau_n,
             float* __restrict__ ydot) {
    const int b = blockIdx.x;
    const int i = threadIdx.x;

    __shared__ float Vs[NN];

    // y[b, 4i .. 4i+3] = {V, m, h, n} : one coalesced float4
    float4 yv = reinterpret_cast<const float4*>(y)[b * NN + i];
    float V = yv.x, m = yv.y, h = yv.z, n = yv.w;
    Vs[i] = V;
    __syncthreads();

    float invC = 1.f / C[i];
    float gna = g_Na[i], gk = g_K[i], gl = g_L[i];
    float m2 = m * m, m3 = m2 * m;
    float n2 = n * n, n3 = n2 * n, n4 = n3 * n;
    float dVNa = V - E_Na[i];
    float dVK  = V - E_K[i];

    // coupling: sum_j negGCC[i][j]*(V_j - V_i); read TRANSPOSE for coalescing.
    float acc = 0.f;
    const float* __restrict__ colT = g_negGCC_T;
    #pragma unroll 16
    for (int j = 0; j < NN; j++)
        acc = fmaf(colT[j * NN + i], Vs[j] - V, acc);

    float Vdot = invC * (-gna * m3 * h * dVNa - gk * n4 * dVK - gl * (V - E_L[i]) + Ic[b]) + acc;
    float mdot = (m_inf[i] - m) / tau_m[i];
    float hdot = (h_inf[i] - h) / tau_h[i];
    float ndot = (n_inf[i] - n) / tau_n[i];

    reinterpret_cast<float4*>(ydot)[b * NN + i] = make_float4(Vdot, mdot, hdot, ndot);

    float dvv = invC * (-gl - gna * h * m3 - gk * n4);
    float jm  = -invC * 3.f * gna * h * m2 * dVNa;
    float jh  = -invC * gna * m3 * dVNa;
    float jn  = -invC * 4.f * gk * n3 * dVK;
    g_state[b * NN + i] = make_float4(dvv, jm, jh, jn);
}

// ---------------------------------------------------------------------
// Kernel 2: stream-fill the full Jacobian (268 MB of STG.128).
// One thread = one float4 = J[b, r, 4j .. 4j+3].
// ---------------------------------------------------------------------
__global__ void __launch_bounds__(256)
fill_kernel(float* __restrict__ J) {
    unsigned tid = blockIdx.x * 256u + threadIdx.x;   // < 16,777,216
    int j    = tid & 127;
    int r    = (tid >> 7) & 511;
    int b    = tid >> 16;
    int comp = r & 3;
    int i    = r >> 2;

    float4 out = make_float4(0.f, 0.f, 0.f, 0.f);
    if (comp == 0) {
        float v = g_negGCC[i * NN + j];     // coalesced across the warp
        if (j == i) {
            float4 st = g_state[b * NN + i];
            v += g_sumGC + st.x;
            out.y = st.y; out.z = st.z; out.w = st.w;
        }
        out.x = v;
    } else if (j == i) {
        float4 d = g_diag4[i];
        float val = (comp == 1) ? d.y : (comp == 2) ? d.z : d.w;
        reinterpret_cast<float*>(&out)[comp] = val;
    }
    reinterpret_cast<float4*>(J)[tid] = out;
}

// ---------------------------------------------------------------------
extern "C" void kernel_launch(void* const* d_in, const int* in_sizes, int n_in,
                              void* d_out, int out_size) {
    const float* y     = (const float*)d_in[0];
    const float* Ic    = (const float*)d_in[1];
    const float* C     = (const float*)d_in[2];
    const float* g_Na  = (const float*)d_in[3];
    const float* E_Na  = (const float*)d_in[4];
    const float* g_K   = (const float*)d_in[5];
    const float* E_K   = (const float*)d_in[6];
    const float* g_L   = (const float*)d_in[7];
    const float* E_L   = (const float*)d_in[8];
    const float* m_inf = (const float*)d_in[9];
    const float* tau_m = (const float*)d_in[10];
    const float* h_inf = (const float*)d_in[11];
    const float* tau_h = (const float*)d_in[12];
    const float* n_inf = (const float*)d_in[13];
    const float* tau_n = (const float*)d_in[14];
    const float* g_C   = (const float*)d_in[15];

    float* out  = (float*)d_out;
    float* ydot = out;                       // B*512 floats
    float* J    = out + (size_t)BB * EE;     // B*512*512 floats

    prep_wide_kernel<<<NN, NN>>>(g_C, C);
    prep_reduce_kernel<<<1, NN>>>(tau_m, tau_h, tau_n);
    point_kernel<<<BB, NN>>>(y, Ic, C, g_Na, E_Na, g_K, E_K, g_L, E_L,
                             m_inf, tau_m, h_inf, tau_h, n_inf, tau_n, ydot);
    // B*512*128 float4s = 16,777,216 threads
    fill_kernel<<<(BB * EE * NN) / 256, 256>>>(J);
}

// round 3
// speedup vs baseline: 1.5176x; 1.0069x over previous
#include <cuda_runtime.h>

// B=256 batches, N=128 neurons, E=4N=512 state dims.
// Output layout: [ydot (B*512 floats)] [J (B*512*512 floats)]
#define NN 128
#define BB 256
#define EE 512

// -------- scratch (__device__ globals; no allocations allowed) --------
__device__ float  g_negGCC  [NN * NN];   // -g_C[i][j] / C[j], row-major (i major)
__device__ float  g_negGCC_T[NN * NN];   // transpose: [j][i]
__device__ float  g_partial [NN];        // per-row partial sums of gC_over_C
__device__ float  g_sumGC;               // sum over all i,j of g_C[i][j]/C[j]
__device__ float4 g_diag4   [NN];        // {0, -1/tau_m, -1/tau_h, -1/tau_n}
__device__ float4 g_state   [BB * NN];   // {dvv, jm, jh, jn} per (b,i)

// ---------------------------------------------------------------------
// Kernel 0a: wide static precompute. 128 blocks x 128 threads,
// block i / thread j handles gC[i][j]. One load+div per thread -> fully
// latency-overlapped. Per-block deterministic shared-tree partial sum.
// ---------------------------------------------------------------------
__global__ void __launch_bounds__(NN)
prep_wide_kernel(const float* __restrict__ gC, const float* __restrict__ C) {
    __shared__ float red[NN];
    const int i = blockIdx.x;
    const int j = threadIdx.x;
    const int k = i * NN + j;

    float v = gC[k] / C[j];          // gC_over_C[i][j]
    g_negGCC[k]            = -v;
    g_negGCC_T[j * NN + i] = -v;

    red[j] = v;
    __syncthreads();
    #pragma unroll
    for (int s = 64; s > 0; s >>= 1) {
        if (j < s) red[j] += red[j + s];
        __syncthreads();
    }
    if (j == 0) g_partial[i] = red[0];
}

// ---------------------------------------------------------------------
// Kernel 0b: deterministic final reduce of 128 partials + diag table.
// 1 block x 128 threads (tiny; all inputs L2-hot by now).
// ---------------------------------------------------------------------
__global__ void __launch_bounds__(NN)
prep_reduce_kernel(const float* __restrict__ tau_m,
                   const float* __restrict__ tau_h,
                   const float* __restrict__ tau_n) {
    __shared__ float red[NN];
    const int t = threadIdx.x;
    red[t] = g_partial[t];
    __syncthreads();
    #pragma unroll
    for (int s = 64; s > 0; s >>= 1) {
        if (t < s) red[t] += red[t + s];
        __syncthreads();
    }
    if (t == 0) g_sumGC = red[0];
    g_diag4[t] = make_float4(0.f, -1.f / tau_m[t], -1.f / tau_h[t], -1.f / tau_n[t]);
}

// ---------------------------------------------------------------------
// Kernel 1: pointwise HH dynamics + coupling matvec.
// Grid: (BB) blocks x NN threads. Thread i of block b handles neuron i.
// ---------------------------------------------------------------------
__global__ void __launch_bounds__(NN)
point_kernel(const float* __restrict__ y,     const float* __restrict__ Ic,
             const float* __restrict__ C,
             const float* __restrict__ g_Na,  const float* __restrict__ E_Na,
             const float* __restrict__ g_K,   const float* __restrict__ E_K,
             const float* __restrict__ g_L,   const float* __restrict__ E_L,
             const float* __restrict__ m_inf, const float* __restrict__ tau_m,
             const float* __restrict__ h_inf, const float* __restrict__ tau_h,
             const float* __restrict__ n_inf, const float* __restrict__ tau_n,
             float* __restrict__ ydot) {
    const int b = blockIdx.x;
    const int i = threadIdx.x;

    __shared__ float Vs[NN];

    // y[b, 4i .. 4i+3] = {V, m, h, n} : one coalesced float4
    float4 yv = reinterpret_cast<const float4*>(y)[b * NN + i];
    float V = yv.x, m = yv.y, h = yv.z, n = yv.w;
    Vs[i] = V;
    __syncthreads();

    float invC = 1.f / C[i];
    float gna = g_Na[i], gk = g_K[i], gl = g_L[i];
    float m2 = m * m, m3 = m2 * m;
    float n2 = n * n, n3 = n2 * n, n4 = n3 * n;
    float dVNa = V - E_Na[i];
    float dVK  = V - E_K[i];

    // coupling: sum_j negGCC[i][j]*(V_j - V_i); read TRANSPOSE for coalescing.
    float acc = 0.f;
    const float* __restrict__ colT = g_negGCC_T;
    #pragma unroll 16
    for (int j = 0; j < NN; j++)
        acc = fmaf(colT[j * NN + i], Vs[j] - V, acc);

    float Vdot = invC * (-gna * m3 * h * dVNa - gk * n4 * dVK - gl * (V - E_L[i]) + Ic[b]) + acc;
    float mdot = (m_inf[i] - m) / tau_m[i];
    float hdot = (h_inf[i] - h) / tau_h[i];
    float ndot = (n_inf[i] - n) / tau_n[i];

    reinterpret_cast<float4*>(ydot)[b * NN + i] = make_float4(Vdot, mdot, hdot, ndot);

    float dvv = invC * (-gl - gna * h * m3 - gk * n4);
    float jm  = -invC * 3.f * gna * h * m2 * dVNa;
    float jh  = -invC * gna * m3 * dVNa;
    float jn  = -invC * 4.f * gk * n3 * dVK;
    g_state[b * NN + i] = make_float4(dvv, jm, jh, jn);
}

// ---------------------------------------------------------------------
// Kernel 2: stream-fill the full Jacobian (268 MB of STG.128).
// One thread = one float4 = J[b, r, 4j .. 4j+3].
// ---------------------------------------------------------------------
__global__ void __launch_bounds__(256)
fill_kernel(float* __restrict__ J) {
    unsigned tid = blockIdx.x * 256u + threadIdx.x;   // < 16,777,216
    int j    = tid & 127;
    int r    = (tid >> 7) & 511;
    int b    = tid >> 16;
    int comp = r & 3;
    int i    = r >> 2;

    float4 out = make_float4(0.f, 0.f, 0.f, 0.f);
    if (comp == 0) {
        float v = g_negGCC[i * NN + j];     // coalesced across the warp
        if (j == i) {
            float4 st = g_state[b * NN + i];
            v += g_sumGC + st.x;
            out.y = st.y; out.z = st.z; out.w = st.w;
        }
        out.x = v;
    } else if (j == i) {
        float4 d = g_diag4[i];
        float val = (comp == 1) ? d.y : (comp == 2) ? d.z : d.w;
        reinterpret_cast<float*>(&out)[comp] = val;
    }
    reinterpret_cast<float4*>(J)[tid] = out;
}

// ---------------------------------------------------------------------
extern "C" void kernel_launch(void* const* d_in, const int* in_sizes, int n_in,
                              void* d_out, int out_size) {
    const float* y     = (const float*)d_in[0];
    const float* Ic    = (const float*)d_in[1];
    const float* C     = (const float*)d_in[2];
    const float* g_Na  = (const float*)d_in[3];
    const float* E_Na  = (const float*)d_in[4];
    const float* g_K   = (const float*)d_in[5];
    const float* E_K   = (const float*)d_in[6];
    const float* g_L   = (const float*)d_in[7];
    const float* E_L   = (const float*)d_in[8];
    const float* m_inf = (const float*)d_in[9];
    const float* tau_m = (const float*)d_in[10];
    const float* h_inf = (const float*)d_in[11];
    const float* tau_h = (const float*)d_in[12];
    const float* n_inf = (const float*)d_in[13];
    const float* tau_n = (const float*)d_in[14];
    const float* g_C   = (const float*)d_in[15];

    float* out  = (float*)d_out;
    float* ydot = out;                       // B*512 floats
    float* J    = out + (size_t)BB * EE;     // B*512*512 floats

    prep_wide_kernel<<<NN, NN>>>(g_C, C);
    prep_reduce_kernel<<<1, NN>>>(tau_m, tau_h, tau_n);
    point_kernel<<<BB, NN>>>(y, Ic, C, g_Na, E_Na, g_K, E_K, g_L, E_L,
                             m_inf, tau_m, h_inf, tau_h, n_inf, tau_n, ydot);
    // B*512*128 float4s = 16,777,216 threads
    fill_kernel<<<(BB * EE * NN) / 256, 256>>>(J);
}

// round 4
// speedup vs baseline: 1.5883x; 1.0466x over previous
#include <cuda_runtime.h>

// B=256 batches, N=128 neurons, E=4N=512 state dims.
// Output layout: [ydot (B*512 floats)] [J (B*512*512 floats)]
#define NN 128
#define BB 256
#define EE 512

// -------- scratch (__device__ globals; no allocations allowed) --------
__device__ float  g_negGCC  [NN * NN];   // -g_C[i][j] / C[j], row-major (i major)
__device__ float  g_negGCC_T[NN * NN];   // transpose: [j][i]
__device__ float  g_partial [NN];        // per-row partial sums of gC_over_C
__device__ float  g_sumGC;               // sum over all i,j of g_C[i][j]/C[j]
__device__ float4 g_diag4   [NN];        // {0, -1/tau_m, -1/tau_h, -1/tau_n}
__device__ float4 g_state   [BB * NN];   // {dvv, jm, jh, jn} per (b,i)

// ---------------------------------------------------------------------
// Kernel 0: wide static precompute. 128 blocks x 128 threads,
// block i / thread j handles gC[i][j]. Block 0 also builds diag4.
// ---------------------------------------------------------------------
__global__ void __launch_bounds__(NN)
prep_wide_kernel(const float* __restrict__ gC, const float* __restrict__ C,
                 const float* __restrict__ tau_m,
                 const float* __restrict__ tau_h,
                 const float* __restrict__ tau_n) {
    __shared__ float red[NN];
    const int i = blockIdx.x;
    const int j = threadIdx.x;
    const int k = i * NN + j;

    float v = gC[k] / C[j];          // gC_over_C[i][j]
    g_negGCC[k]            = -v;
    g_negGCC_T[j * NN + i] = -v;

    if (i == 0)
        g_diag4[j] = make_float4(0.f, -1.f / tau_m[j], -1.f / tau_h[j], -1.f / tau_n[j]);

    red[j] = v;
    __syncthreads();
    #pragma unroll
    for (int s = 64; s > 0; s >>= 1) {
        if (j < s) red[j] += red[j + s];
        __syncthreads();
    }
    if (j == 0) g_partial[i] = red[0];
}

// ---------------------------------------------------------------------
// Kernel 1: pointwise HH dynamics + coupling matvec.
// Grid: (BB) blocks x NN threads. Thread i of block b handles neuron i.
// Block 0 additionally performs the deterministic final reduce of
// g_partial -> g_sumGC (consumed only by fill_kernel, launched after).
// ---------------------------------------------------------------------
__global__ void __launch_bounds__(NN)
point_kernel(const float* __restrict__ y,     const float* __restrict__ Ic,
             const float* __restrict__ C,
             const float* __restrict__ g_Na,  const float* __restrict__ E_Na,
             const float* __restrict__ g_K,   const float* __restrict__ E_K,
             const float* __restrict__ g_L,   const float* __restrict__ E_L,
             const float* __restrict__ m_inf, const float* __restrict__ tau_m,
             const float* __restrict__ h_inf, const float* __restrict__ tau_h,
             const float* __restrict__ n_inf, const float* __restrict__ tau_n,
             float* __restrict__ ydot) {
    const int b = blockIdx.x;
    const int i = threadIdx.x;

    __shared__ float Vs[NN];

    // y[b, 4i .. 4i+3] = {V, m, h, n} : one coalesced float4
    float4 yv = reinterpret_cast<const float4*>(y)[b * NN + i];
    float V = yv.x, m = yv.y, h = yv.z, n = yv.w;
    Vs[i] = V;
    __syncthreads();

    float invC = 1.f / C[i];
    float gna = g_Na[i], gk = g_K[i], gl = g_L[i];
    float m2 = m * m, m3 = m2 * m;
    float n2 = n * n, n3 = n2 * n, n4 = n3 * n;
    float dVNa = V - E_Na[i];
    float dVK  = V - E_K[i];

    // coupling: sum_j negGCC[i][j]*(V_j - V_i); read TRANSPOSE for coalescing.
    // 4 independent accumulators for ILP; fixed combine order (deterministic).
    float a0 = 0.f, a1 = 0.f, a2 = 0.f, a3 = 0.f;
    const float* __restrict__ colT = g_negGCC_T;
    #pragma unroll 8
    for (int j = 0; j < NN; j += 4) {
        a0 = fmaf(colT[(j + 0) * NN + i], Vs[j + 0] - V, a0);
        a1 = fmaf(colT[(j + 1) * NN + i], Vs[j + 1] - V, a1);
        a2 = fmaf(colT[(j + 2) * NN + i], Vs[j + 2] - V, a2);
        a3 = fmaf(colT[(j + 3) * NN + i], Vs[j + 3] - V, a3);
    }
    float acc = (a0 + a1) + (a2 + a3);

    float Vdot = invC * (-gna * m3 * h * dVNa - gk * n4 * dVK - gl * (V - E_L[i]) + Ic[b]) + acc;
    float mdot = (m_inf[i] - m) / tau_m[i];
    float hdot = (h_inf[i] - h) / tau_h[i];
    float ndot = (n_inf[i] - n) / tau_n[i];

    reinterpret_cast<float4*>(ydot)[b * NN + i] = make_float4(Vdot, mdot, hdot, ndot);

    float dvv = invC * (-gl - gna * h * m3 - gk * n4);
    float jm  = -invC * 3.f * gna * h * m2 * dVNa;
    float jh  = -invC * gna * m3 * dVNa;
    float jn  = -invC * 4.f * gk * n3 * dVK;
    g_state[b * NN + i] = make_float4(dvv, jm, jh, jn);

    // Tail: block 0 reduces the 128 per-row partials (deterministic tree).
    if (b == 0) {
        __syncthreads();               // reuse Vs as scratch safely
        Vs[i] = g_partial[i];
        __syncthreads();
        #pragma unroll
        for (int s = 64; s > 0; s >>= 1) {
            if (i < s) Vs[i] += Vs[i + s];
            __syncthreads();
        }
        if (i == 0) g_sumGC = Vs[0];
    }
}

// ---------------------------------------------------------------------
// Kernel 2: stream-fill the full Jacobian (268 MB of STG.128).
// Grid: x = 256 row-pairs, y = 128 batch-pairs. Block = 256 threads
// (2 rows x 128 col-groups). Each thread emits TWO float4s: same (r, j)
// for batches b and b+128 -> one negGCC load + one index decode per
// 32 bytes stored, block-uniform comp/i (uniform datapath), 2-deep
// store ILP, streaming (.cs) stores.
// ---------------------------------------------------------------------
__global__ void __launch_bounds__(256)
fill_kernel(float* __restrict__ J) {
    const int j    = threadIdx.x & 127;
    const int half = threadIdx.x >> 7;            // 0 or 1
    const int r    = blockIdx.x * 2 + half;       // 0..511  (warp-uniform)
    const int b    = blockIdx.y;                  // batches b and b+128
    const int comp = r & 3;
    const int i    = r >> 2;

    float4 o0 = make_float4(0.f, 0.f, 0.f, 0.f);
    if (comp == 0) o0.x = g_negGCC[i * NN + j];   // coalesced across warp
    float4 o1 = o0;

    if (j == i) {
        if (comp == 0) {
            float s = g_sumGC;
            float4 s0 = g_state[b * NN + i];
            float4 s1 = g_state[(b + 128) * NN + i];
            o0.x += s + s0.x; o0.y = s0.y; o0.z = s0.z; o0.w = s0.w;
            o1.x += s + s1.x; o1.y = s1.y; o1.z = s1.z; o1.w = s1.w;
        } else {
            float4 d = g_diag4[i];
            float val = (comp == 1) ? d.y : (comp == 2) ? d.z : d.w;
            reinterpret_cast<float*>(&o0)[comp] = val;
            reinterpret_cast<float*>(&o1)[comp] = val;
        }
    }

    // float4 index: b*EE*NN + r*NN + j  (max 16.7M, fits 32-bit)
    unsigned idx0 = (unsigned)b * (EE * NN) + (unsigned)r * NN + j;
    unsigned idx1 = idx0 + 128u * (EE * NN);
    __stcs(reinterpret_cast<float4*>(J) + idx0, o0);
    __stcs(reinterpret_cast<float4*>(J) + idx1, o1);
}

// ---------------------------------------------------------------------
extern "C" void kernel_launch(void* const* d_in, const int* in_sizes, int n_in,
                              void* d_out, int out_size) {
    const float* y     = (const float*)d_in[0];
    const float* Ic    = (const float*)d_in[1];
    const float* C     = (const float*)d_in[2];
    const float* g_Na  = (const float*)d_in[3];
    const float* E_Na  = (const float*)d_in[4];
    const float* g_K   = (const float*)d_in[5];
    const float* E_K   = (const float*)d_in[6];
    const float* g_L   = (const float*)d_in[7];
    const float* E_L   = (const float*)d_in[8];
    const float* m_inf = (const float*)d_in[9];
    const float* tau_m = (const float*)d_in[10];
    const float* h_inf = (const float*)d_in[11];
    const float* tau_h = (const float*)d_in[12];
    const float* n_inf = (const float*)d_in[13];
    const float* tau_n = (const float*)d_in[14];
    const float* g_C   = (const float*)d_in[15];

    float* out  = (float*)d_out;
    float* ydot = out;                       // B*512 floats
    float* J    = out + (size_t)BB * EE;     // B*512*512 floats

    prep_wide_kernel<<<NN, NN>>>(g_C, C, tau_m, tau_h, tau_n);
    point_kernel<<<BB, NN>>>(y, Ic, C, g_Na, E_Na, g_K, E_K, g_L, E_L,
                             m_inf, tau_m, h_inf, tau_h, n_inf, tau_n, ydot);
    fill_kernel<<<dim3(EE / 2, BB / 2), 256>>>(J);
}